// round 1
// baseline (speedup 1.0000x reference)
#include <cuda_runtime.h>
#include <math.h>

#define NN 2048
#define TT 64
#define FF 16
#define HH 64
#define LL 16
#define KK 10
#define NKEYS (NN*LL)            // 32768
#define KBLOCKS 8
#define KEYS_PER_KB (NKEYS/KBLOCKS)  // 4096
#define TILE_KEYS 128

// ---------------- scratch (static device memory; no allocation) ----------------
__device__ float g_htail[NN*LL*HH];        // last-16 hidden states   (8 MB)
__device__ float g_q[NN*HH];               // queries                 (0.5 MB)
__device__ float g_keys[NN*LL*HH];         // projected keys          (8 MB)
__device__ float g_pv[NN*KBLOCKS*KK];      // partial top-k values
__device__ int   g_pi[NN*KBLOCKS*KK];      // partial top-k indices

// ============================ K1: GRU ============================
// 128 blocks x 256 threads; block owns 16 samples for all 64 steps.
// Shared: W_hh (transposed-row padded), W_ih, h-state, gate buffers.
#define GRU_SMEM_FLOATS (192*68 + 192*20 + 16*68 + 16*20 + 16*192 + 16*192 + 192 + 192)

__global__ void __launch_bounds__(256, 1) gru_kernel(
    const float* __restrict__ x,
    const float* __restrict__ Wih, const float* __restrict__ Whh,
    const float* __restrict__ bih, const float* __restrict__ bhh)
{
    extern __shared__ float sm[];
    float* sWhh = sm;                         // 192*68
    float* sWih = sWhh + 192*68;              // 192*20
    float* sh   = sWih + 192*20;              // 16*68
    float* sxt  = sh   + 16*68;               // 16*20
    float* sgx  = sxt  + 16*20;               // 16*192
    float* sgh  = sgx  + 16*192;              // 16*192
    float* sbih = sgh  + 16*192;              // 192
    float* sbhh = sbih + 192;                 // 192

    const int tid = threadIdx.x;
    const int n0  = blockIdx.x * 16;

    for (int i = tid; i < 192*64; i += 256) { int j = i >> 6, k = i & 63; sWhh[j*68+k] = Whh[i]; }
    for (int i = tid; i < 192*16; i += 256) { int j = i >> 4, k = i & 15; sWih[j*20+k] = Wih[i]; }
    if (tid < 192) { sbih[tid] = bih[tid]; sbhh[tid] = bhh[tid]; }
    for (int i = tid; i < 16*68; i += 256) sh[i] = 0.0f;
    __syncthreads();

    const int jl = tid & 63;     // output-gate lane (j = jl + 64u)
    const int rb = tid >> 6;     // row block (rows rb*4 .. rb*4+3)

    for (int t = 0; t < TT; ++t) {
        // ---- A: stage x_t for the 16 rows ----
        {
            int r = tid >> 4, f = tid & 15;
            sxt[r*20 + f] = x[((n0 + r)*TT + t)*FF + f];
        }
        __syncthreads();

        // ---- B: gate pre-activations  gx = x@Wih^T, gh = h@Whh^T ----
        float accx[4][3], acch[4][3];
        #pragma unroll
        for (int i = 0; i < 4; ++i)
            #pragma unroll
            for (int u = 0; u < 3; ++u) { accx[i][u] = 0.0f; acch[i][u] = 0.0f; }

        #pragma unroll
        for (int k = 0; k < 16; k += 4) {
            float4 wv[3];
            #pragma unroll
            for (int u = 0; u < 3; ++u) wv[u] = *(const float4*)&sWih[(jl + 64*u)*20 + k];
            #pragma unroll
            for (int i = 0; i < 4; ++i) {
                float4 xv = *(const float4*)&sxt[(rb*4 + i)*20 + k];
                #pragma unroll
                for (int u = 0; u < 3; ++u) {
                    accx[i][u] = fmaf(xv.x, wv[u].x, accx[i][u]);
                    accx[i][u] = fmaf(xv.y, wv[u].y, accx[i][u]);
                    accx[i][u] = fmaf(xv.z, wv[u].z, accx[i][u]);
                    accx[i][u] = fmaf(xv.w, wv[u].w, accx[i][u]);
                }
            }
        }
        #pragma unroll
        for (int k = 0; k < 64; k += 4) {
            float4 wv[3];
            #pragma unroll
            for (int u = 0; u < 3; ++u) wv[u] = *(const float4*)&sWhh[(jl + 64*u)*68 + k];
            #pragma unroll
            for (int i = 0; i < 4; ++i) {
                float4 hv = *(const float4*)&sh[(rb*4 + i)*68 + k];
                #pragma unroll
                for (int u = 0; u < 3; ++u) {
                    acch[i][u] = fmaf(hv.x, wv[u].x, acch[i][u]);
                    acch[i][u] = fmaf(hv.y, wv[u].y, acch[i][u]);
                    acch[i][u] = fmaf(hv.z, wv[u].z, acch[i][u]);
                    acch[i][u] = fmaf(hv.w, wv[u].w, acch[i][u]);
                }
            }
        }
        #pragma unroll
        for (int i = 0; i < 4; ++i) {
            int r = rb*4 + i;
            #pragma unroll
            for (int u = 0; u < 3; ++u) {
                int j = jl + 64*u;
                sgx[r*192 + j] = accx[i][u] + sbih[j];
                sgh[r*192 + j] = acch[i][u] + sbhh[j];
            }
        }
        __syncthreads();

        // ---- C: nonlinearity + state update ----
        {
            int d = tid & 63, rb2 = tid >> 6;
            #pragma unroll
            for (int i = 0; i < 4; ++i) {
                int r = rb2*4 + i;
                float xr = sgx[r*192 + d],       hr = sgh[r*192 + d];
                float xz = sgx[r*192 + 64 + d],  hz = sgh[r*192 + 64 + d];
                float xn = sgx[r*192 + 128 + d], hn = sgh[r*192 + 128 + d];
                float rg = 1.0f / (1.0f + __expf(-(xr + hr)));
                float zg = 1.0f / (1.0f + __expf(-(xz + hz)));
                float ng = tanhf(xn + rg * hn);
                float ho = sh[r*68 + d];
                float hnew = (1.0f - zg) * ng + zg * ho;
                sh[r*68 + d] = hnew;
                if (t >= TT - LL)
                    g_htail[((n0 + r)*LL + (t - (TT - LL)))*HH + d] = hnew;
            }
        }
        __syncthreads();
    }
}

// ============================ K2: q/k projections ============================
__global__ void __launch_bounds__(256) qk_kernel(const float* __restrict__ Wq,
                                                 const float* __restrict__ Wk)
{
    __shared__ float sWq[64*68];
    __shared__ float sWk[64*68];
    __shared__ float sht[16*68];
    const int tid = threadIdx.x;
    const int n   = blockIdx.x;

    for (int i = tid; i < 64*64; i += 256) { int j = i >> 6, k = i & 63; sWq[j*68+k] = Wq[i]; sWk[j*68+k] = Wk[i]; }
    for (int i = tid; i < 16*64; i += 256) { int l = i >> 6, k = i & 63; sht[l*68+k] = g_htail[(n*16 + l)*64 + k]; }
    __syncthreads();

    const int tx = tid & 15, l = tid >> 4;
    float acc[4] = {0.f, 0.f, 0.f, 0.f};
    #pragma unroll
    for (int k = 0; k < 64; k += 4) {
        float4 hv = *(const float4*)&sht[l*68 + k];
        #pragma unroll
        for (int u = 0; u < 4; ++u) {
            float4 wv = *(const float4*)&sWk[(tx + 16*u)*68 + k];
            acc[u] = fmaf(hv.x, wv.x, fmaf(hv.y, wv.y, fmaf(hv.z, wv.z, fmaf(hv.w, wv.w, acc[u]))));
        }
    }
    #pragma unroll
    for (int u = 0; u < 4; ++u)
        g_keys[(n*16 + l)*64 + tx + 16*u] = acc[u];

    if (tid < 64) {
        float a = 0.f;
        #pragma unroll
        for (int k = 0; k < 64; k += 4) {
            float4 hv = *(const float4*)&sht[15*68 + k];
            float4 wv = *(const float4*)&sWq[tid*68 + k];
            a = fmaf(hv.x, wv.x, fmaf(hv.y, wv.y, fmaf(hv.z, wv.z, fmaf(hv.w, wv.w, a))));
        }
        g_q[n*64 + tid] = a;
    }
}

// ============================ K3: scores GEMM + fused partial top-k ============================
#define K3_SMEM_BYTES ((64*68 + 128*68 + 64*10 + 64)*4 + (64*10 + 64)*4)

__device__ __forceinline__ void topk_insert(float* sv, int* si, volatile float* svmin,
                                            int* slock, int r, float val, int idx)
{
    bool done = false;
    while (!done) {
        if (atomicCAS(&slock[r], 0, 1) == 0) {
            float mn = sv[r*10]; int mp = 0;
            #pragma unroll
            for (int e = 1; e < 10; ++e) { float v = sv[r*10+e]; if (v < mn) { mn = v; mp = e; } }
            if (val > mn) {
                sv[r*10+mp] = val; si[r*10+mp] = idx;
                float nm = sv[r*10];
                #pragma unroll
                for (int e = 1; e < 10; ++e) { float v = sv[r*10+e]; if (v < nm) nm = v; }
                svmin[r] = nm;
            }
            __threadfence_block();
            atomicExch(&slock[r], 0);
            done = true;
        }
    }
}

__global__ void __launch_bounds__(256, 2) scores_topk_kernel()
{
    extern __shared__ float sm[];
    float* sq    = sm;                 // 64*68
    float* sk    = sq + 64*68;         // 128*68
    float* sv    = sk + 128*68;        // 64*10
    float* svminS= sv + 640;           // 64
    int*   si    = (int*)(svminS + 64);// 64*10
    int*   slock = si + 640;           // 64

    const int tid = threadIdx.x;
    const int qb  = blockIdx.x;        // 0..31
    const int kb  = blockIdx.y;        // 0..7

    for (int i = tid; i < 64*16; i += 256) {   // load queries as float4 chunks
        int r = i >> 4, c = i & 15;
        *(float4*)&sq[r*68 + c*4] = *(const float4*)&g_q[(qb*64 + r)*64 + c*4];
    }
    for (int i = tid; i < 640; i += 256) sv[i] = -INFINITY;
    if (tid < 64) { svminS[tid] = -INFINITY; slock[tid] = 0; }
    __syncthreads();

    const int tx = tid & 15, ty = tid >> 4;
    const int kbase = kb * KEYS_PER_KB;
    volatile float* vmin = svminS;

    for (int tt = 0; tt < KEYS_PER_KB / TILE_KEYS; ++tt) {
        for (int i = tid; i < 128*16; i += 256) {
            int kr = i >> 4, c = i & 15;
            *(float4*)&sk[kr*68 + c*4] =
                *(const float4*)&g_keys[(kbase + tt*128 + kr)*64 + c*4];
        }
        __syncthreads();

        float acc[4][8];
        #pragma unroll
        for (int i = 0; i < 4; ++i)
            #pragma unroll
            for (int u = 0; u < 8; ++u) acc[i][u] = 0.0f;

        #pragma unroll
        for (int k = 0; k < 64; k += 4) {
            float4 kv[8];
            #pragma unroll
            for (int u = 0; u < 8; ++u) kv[u] = *(const float4*)&sk[(tx + 16*u)*68 + k];
            #pragma unroll
            for (int i = 0; i < 4; ++i) {
                float4 qv = *(const float4*)&sq[(ty + 16*i)*68 + k];
                #pragma unroll
                for (int u = 0; u < 8; ++u) {
                    acc[i][u] = fmaf(qv.x, kv[u].x, acc[i][u]);
                    acc[i][u] = fmaf(qv.y, kv[u].y, acc[i][u]);
                    acc[i][u] = fmaf(qv.z, kv[u].z, acc[i][u]);
                    acc[i][u] = fmaf(qv.w, kv[u].w, acc[i][u]);
                }
            }
        }

        #pragma unroll
        for (int i = 0; i < 4; ++i) {
            int r = ty + 16*i;
            int qrow = qb*64 + r;
            float thr = vmin[r];
            #pragma unroll
            for (int u = 0; u < 8; ++u) {
                int g = kbase + tt*128 + tx + 16*u;
                float s = acc[i][u];
                if ((g >> 4) == qrow) s = -1e9f;   // mask self (m == n)
                if (s > thr) {
                    topk_insert(sv, si, vmin, slock, r, s, g);
                    thr = vmin[r];
                }
            }
        }
        __syncthreads();
    }

    if (tid < 64) {
        int qrow = qb*64 + tid;
        #pragma unroll
        for (int e = 0; e < 10; ++e) {
            g_pv[qrow*80 + kb*10 + e] = sv[tid*10 + e];
            g_pi[qrow*80 + kb*10 + e] = si[tid*10 + e];
        }
    }
}

// ============================ K4: merge + softmax + gather + MLP ============================
__global__ void __launch_bounds__(256) final_kernel(
    const float* __restrict__ x,
    const float* __restrict__ W1, const float* __restrict__ b1,
    const float* __restrict__ W2, const float* __restrict__ b2,
    float* __restrict__ out)
{
    const int warp = threadIdx.x >> 5, lane = threadIdx.x & 31;
    const int n = blockIdx.x * 8 + warp;

    float cv[3]; int ci[3];
    #pragma unroll
    for (int s = 0; s < 3; ++s) {
        int c = lane + 32*s;
        if (c < 80) { cv[s] = g_pv[n*80 + c]; ci[s] = g_pi[n*80 + c]; }
        else        { cv[s] = -INFINITY;      ci[s] = -1000 - s; }
    }

    float topv[10]; int topi[10];
    #pragma unroll
    for (int it = 0; it < 10; ++it) {
        float bv = cv[0]; int bi = ci[0];
        if (cv[1] > bv) { bv = cv[1]; bi = ci[1]; }
        if (cv[2] > bv) { bv = cv[2]; bi = ci[2]; }
        #pragma unroll
        for (int off = 16; off; off >>= 1) {
            float ov = __shfl_xor_sync(0xffffffffu, bv, off);
            int   oi = __shfl_xor_sync(0xffffffffu, bi, off);
            if (ov > bv || (ov == bv && oi < bi)) { bv = ov; bi = oi; }
        }
        topv[it] = bv; topi[it] = bi;
        #pragma unroll
        for (int s = 0; s < 3; ++s)
            if (ci[s] == bi) { cv[s] = -INFINITY; ci[s] = -2000 - s; }
    }

    // softmax over the 10 values (topv[0] is the max)
    float w[10]; float sumw = 0.0f;
    #pragma unroll
    for (int e = 0; e < 10; ++e) { w[e] = expf(topv[e] - topv[0]); sumw += w[e]; }
    float inv = 1.0f / sumw;

    if (lane < 16) {
        float wf = 0.0f;   // weighted feature for f = lane
        #pragma unroll
        for (int e = 0; e < 10; ++e) {
            int m  = topi[e] >> 4;
            int ti = 48 + (topi[e] & 15);
            wf = fmaf(w[e] * inv, x[(m*TT + ti)*FF + lane], wf);
        }
        float hid = b1[lane];
        #pragma unroll
        for (int f = 0; f < 16; ++f)
            hid = fmaf(W1[lane*16 + f], __shfl_sync(0xffffu, wf, f), hid);
        hid = hid > 0.0f ? hid : 0.01f * hid;
        float val = hid * W2[lane];
        #pragma unroll
        for (int off = 8; off; off >>= 1)
            val += __shfl_xor_sync(0xffffu, val, off);
        if (lane == 0) out[n] = val + b2[0];
    }
}

// ============================ launch ============================
extern "C" void kernel_launch(void* const* d_in, const int* in_sizes, int n_in,
                              void* d_out, int out_size)
{
    const float* x   = (const float*)d_in[0];
    const float* Wih = (const float*)d_in[1];
    const float* Whh = (const float*)d_in[2];
    const float* bih = (const float*)d_in[3];
    const float* bhh = (const float*)d_in[4];
    const float* Wq  = (const float*)d_in[5];
    const float* Wk  = (const float*)d_in[6];
    const float* W1  = (const float*)d_in[7];
    const float* b1  = (const float*)d_in[8];
    const float* W2  = (const float*)d_in[9];
    const float* b2  = (const float*)d_in[10];
    float* out = (float*)d_out;

    const int gru_smem = GRU_SMEM_FLOATS * 4;
    cudaFuncSetAttribute(gru_kernel, cudaFuncAttributeMaxDynamicSharedMemorySize, gru_smem);
    cudaFuncSetAttribute(scores_topk_kernel, cudaFuncAttributeMaxDynamicSharedMemorySize, K3_SMEM_BYTES);

    gru_kernel<<<NN/16, 256, gru_smem>>>(x, Wih, Whh, bih, bhh);
    qk_kernel<<<NN, 256>>>(Wq, Wk);
    dim3 g3(NN/64, KBLOCKS);
    scores_topk_kernel<<<g3, 256, K3_SMEM_BYTES>>>();
    final_kernel<<<NN/8, 256>>>(x, W1, b1, W2, b2, out);
}

// round 3
// speedup vs baseline: 1.1508x; 1.1508x over previous
#include <cuda_runtime.h>
#include <math.h>
#include <stdint.h>

#define NN 2048
#define TT 64
#define FF 16
#define HH 64
#define LL 16
#define KK 10
#define NKEYS (NN*LL)            // 32768
#define KBLOCKS 8
#define KEYS_PER_KB (NKEYS/KBLOCKS)  // 4096
#define TILE_KEYS 128

// ---------------- scratch (static device memory; no allocation) ----------------
__device__ float g_xp[NN*TT*192];          // precomputed input gates (+b_ih)  (~100MB)
__device__ float g_htail[NN*LL*HH];        // last-16 hidden states
__device__ float g_q[NN*HH];               // queries
__device__ float g_keys[NN*LL*HH];         // projected keys
__device__ float g_pv[NN*KBLOCKS*KK];      // partial top-k values
__device__ int   g_pi[NN*KBLOCKS*KK];      // partial top-k indices

// ---------------- packed fp32x2 helpers ----------------
typedef unsigned long long u64t;
__device__ __forceinline__ void ffma2(u64t &d, u64t a, u64t b) {
    asm("fma.rn.f32x2 %0, %1, %2, %3;" : "=l"(d) : "l"(a), "l"(b), "l"(d));
}
__device__ __forceinline__ float f2sum(u64t v) {
    return __uint_as_float((uint32_t)v) + __uint_as_float((uint32_t)(v >> 32));
}

// ============================ K0: xp = x @ W_ih^T + b_ih ============================
// grid 4096 x 192 threads; block handles 32 (n,t) rows; thread j owns one output column.
__global__ void __launch_bounds__(192) xp_kernel(
    const float* __restrict__ x,
    const float* __restrict__ Wih, const float* __restrict__ bih)
{
    __shared__ float sW[192*16];
    __shared__ float sx[32*16];
    __shared__ float sb[192];
    const int tid = threadIdx.x;
    const int row0 = blockIdx.x * 32;

    for (int i = tid; i < 192*16; i += 192) sW[i] = Wih[i];
    for (int i = tid; i < 32*16; i += 192)  sx[i] = x[row0*16 + i];
    sb[tid] = bih[tid];
    __syncthreads();

    const int j = tid;
    u64t w2[8];
    #pragma unroll
    for (int q = 0; q < 8; ++q) w2[q] = *(const u64t*)&sW[j*16 + q*2];
    const float bj = sb[j];

    #pragma unroll 4
    for (int r = 0; r < 32; ++r) {
        u64t acc = 0;
        #pragma unroll
        for (int q = 0; q < 8; ++q)
            ffma2(acc, *(const u64t*)&sx[r*16 + q*2], w2[q]);
        g_xp[(row0 + r)*192 + j] = f2sum(acc) + bj;
    }
}

// ============================ K1: GRU recurrence (gh only) ============================
// 128 blocks x 256 threads; block owns 16 samples for all 64 steps.
#define WS 66   // conflict-free stride for LDS.64 access patterns
#define GRU_SMEM_FLOATS (192*WS + 16*WS + 192)

__global__ void __launch_bounds__(256, 1) gru_kernel(const float* __restrict__ Whh,
                                                     const float* __restrict__ bhh)
{
    extern __shared__ float sm[];
    float* sWhh = sm;               // 192*66
    float* sh   = sWhh + 192*WS;    // 16*66
    float* sbhh = sh + 16*WS;       // 192

    const int tid = threadIdx.x;
    const int n0  = blockIdx.x * 16;

    for (int i = tid; i < 192*64; i += 256) { int j = i >> 6, k = i & 63; sWhh[j*WS + k] = Whh[i]; }
    if (tid < 192) sbhh[tid] = bhh[tid];
    for (int i = tid; i < 16*WS; i += 256) sh[i] = 0.0f;
    __syncthreads();

    const int jl = tid & 63;     // gate lane (j = jl + 64u) == hidden dim d in phase C
    const int rb = tid >> 6;     // rows rb*4 .. rb*4+3

    const float b_r = sbhh[jl];
    const float b_z = sbhh[64 + jl];
    const float b_n = sbhh[128 + jl];

    for (int t = 0; t < TT; ++t) {
        // prefetch xp for this step (hidden under the FMA loop)
        float xr[4], xz[4], xn[4];
        #pragma unroll
        for (int i = 0; i < 4; ++i) {
            const float* xpp = &g_xp[((n0 + rb*4 + i)*TT + t)*192];
            xr[i] = xpp[jl]; xz[i] = xpp[64 + jl]; xn[i] = xpp[128 + jl];
        }

        // gh = h @ Whh^T (packed f32x2 accumulate)
        u64t acc2[4][3];
        #pragma unroll
        for (int i = 0; i < 4; ++i)
            #pragma unroll
            for (int u = 0; u < 3; ++u) acc2[i][u] = 0;

        #pragma unroll
        for (int kc = 0; kc < 64; kc += 4) {
            u64t wa[3], wb[3];
            #pragma unroll
            for (int u = 0; u < 3; ++u) {
                const float* wp = &sWhh[(jl + 64*u)*WS + kc];
                wa[u] = *(const u64t*)wp;
                wb[u] = *(const u64t*)(wp + 2);
            }
            #pragma unroll
            for (int i = 0; i < 4; ++i) {
                const float* hp = &sh[(rb*4 + i)*WS + kc];
                u64t ha = *(const u64t*)hp;
                u64t hb = *(const u64t*)(hp + 2);
                #pragma unroll
                for (int u = 0; u < 3; ++u) {
                    ffma2(acc2[i][u], ha, wa[u]);
                    ffma2(acc2[i][u], hb, wb[u]);
                }
            }
        }
        __syncthreads();   // h fully consumed by all threads

        // nonlinearity + state update (this thread computed exactly the gates it needs)
        #pragma unroll
        for (int i = 0; i < 4; ++i) {
            int r = rb*4 + i;
            float hr = f2sum(acc2[i][0]) + b_r;
            float hz = f2sum(acc2[i][1]) + b_z;
            float hn = f2sum(acc2[i][2]) + b_n;
            float rg = 1.0f / (1.0f + __expf(-(xr[i] + hr)));
            float zg = 1.0f / (1.0f + __expf(-(xz[i] + hz)));
            float targ = xn[i] + rg * hn;
            float e2 = __expf(2.0f * targ);
            float ng = 1.0f - 2.0f / (e2 + 1.0f);
            float ho = sh[r*WS + jl];
            float hnew = (1.0f - zg) * ng + zg * ho;
            sh[r*WS + jl] = hnew;
            if (t >= TT - LL)
                g_htail[((n0 + r)*LL + (t - (TT - LL)))*HH + jl] = hnew;
        }
        __syncthreads();   // h updated before next step's reads
    }
}

// ============================ K2: q/k projections ============================
__global__ void __launch_bounds__(256) qk_kernel(const float* __restrict__ Wq,
                                                 const float* __restrict__ Wk)
{
    __shared__ float sWq[64*68];
    __shared__ float sWk[64*68];
    __shared__ float sht[16*68];
    const int tid = threadIdx.x;
    const int n   = blockIdx.x;

    for (int i = tid; i < 64*64; i += 256) { int j = i >> 6, k = i & 63; sWq[j*68+k] = Wq[i]; sWk[j*68+k] = Wk[i]; }
    for (int i = tid; i < 16*64; i += 256) { int l = i >> 6, k = i & 63; sht[l*68+k] = g_htail[(n*16 + l)*64 + k]; }
    __syncthreads();

    const int tx = tid & 15, l = tid >> 4;
    float acc[4] = {0.f, 0.f, 0.f, 0.f};
    #pragma unroll
    for (int k = 0; k < 64; k += 4) {
        float4 hv = *(const float4*)&sht[l*68 + k];
        #pragma unroll
        for (int u = 0; u < 4; ++u) {
            float4 wv = *(const float4*)&sWk[(tx + 16*u)*68 + k];
            acc[u] = fmaf(hv.x, wv.x, fmaf(hv.y, wv.y, fmaf(hv.z, wv.z, fmaf(hv.w, wv.w, acc[u]))));
        }
    }
    #pragma unroll
    for (int u = 0; u < 4; ++u)
        g_keys[(n*16 + l)*64 + tx + 16*u] = acc[u];

    if (tid < 64) {
        float a = 0.f;
        #pragma unroll
        for (int k = 0; k < 64; k += 4) {
            float4 hv = *(const float4*)&sht[15*68 + k];
            float4 wv = *(const float4*)&sWq[tid*68 + k];
            a = fmaf(hv.x, wv.x, fmaf(hv.y, wv.y, fmaf(hv.z, wv.z, fmaf(hv.w, wv.w, a))));
        }
        g_q[n*64 + tid] = a;
    }
}

// ============================ K3: scores GEMM (f32x2) + fused partial top-k ============================
#define K3_SMEM_BYTES ((64*WS + 128*WS + 640 + 64)*4 + (640 + 64)*4)

__device__ __forceinline__ void topk_insert(float* sv, int* si, volatile float* svmin,
                                            int* slock, int r, float val, int idx)
{
    bool done = false;
    while (!done) {
        if (atomicCAS(&slock[r], 0, 1) == 0) {
            float mn = sv[r*10]; int mp = 0;
            #pragma unroll
            for (int e = 1; e < 10; ++e) { float v = sv[r*10+e]; if (v < mn) { mn = v; mp = e; } }
            if (val > mn) {
                sv[r*10+mp] = val; si[r*10+mp] = idx;
                float nm = sv[r*10];
                #pragma unroll
                for (int e = 1; e < 10; ++e) { float v = sv[r*10+e]; if (v < nm) nm = v; }
                svmin[r] = nm;
            }
            __threadfence_block();
            atomicExch(&slock[r], 0);
            done = true;
        }
    }
}

__global__ void __launch_bounds__(256, 2) scores_topk_kernel()
{
    extern __shared__ float sm[];
    float* sq    = sm;                   // 64*66
    float* sk    = sq + 64*WS;           // 128*66
    float* sv    = sk + 128*WS;          // 64*10
    float* svminS= sv + 640;             // 64
    int*   si    = (int*)(svminS + 64);  // 64*10
    int*   slock = si + 640;             // 64

    const int tid = threadIdx.x;
    const int qb  = blockIdx.x;        // 0..31
    const int kb  = blockIdx.y;        // 0..7

    for (int i = tid; i < 64*16; i += 256) {
        int r = i >> 4, c = (i & 15)*4;
        float4 v = *(const float4*)&g_q[(qb*64 + r)*64 + c];
        u64t* d = (u64t*)&sq[r*WS + c];
        d[0] = ((u64t*)&v)[0]; d[1] = ((u64t*)&v)[1];
    }
    for (int i = tid; i < 640; i += 256) sv[i] = -INFINITY;
    if (tid < 64) { svminS[tid] = -INFINITY; slock[tid] = 0; }
    __syncthreads();

    const int tx = tid & 15, ty = tid >> 4;
    const int kbase0 = kb * KEYS_PER_KB;
    volatile float* vmin = svminS;

    for (int tt = 0; tt < KEYS_PER_KB / TILE_KEYS; ++tt) {
        const int kbase = kbase0 + tt*TILE_KEYS;
        for (int i = tid; i < 128*16; i += 256) {
            int kr = i >> 4, c = (i & 15)*4;
            float4 v = *(const float4*)&g_keys[(kbase + kr)*64 + c];
            u64t* d = (u64t*)&sk[kr*WS + c];
            d[0] = ((u64t*)&v)[0]; d[1] = ((u64t*)&v)[1];
        }
        __syncthreads();

        u64t acc2[4][8];
        #pragma unroll
        for (int i = 0; i < 4; ++i)
            #pragma unroll
            for (int u = 0; u < 8; ++u) acc2[i][u] = 0;

        #pragma unroll
        for (int kc = 0; kc < 64; kc += 4) {
            u64t kva[8], kvb[8];
            #pragma unroll
            for (int u = 0; u < 8; ++u) {
                const float* kp = &sk[(tx + 16*u)*WS + kc];
                kva[u] = *(const u64t*)kp;
                kvb[u] = *(const u64t*)(kp + 2);
            }
            #pragma unroll
            for (int i = 0; i < 4; ++i) {
                const float* qp = &sq[(ty + 16*i)*WS + kc];
                u64t qa = *(const u64t*)qp;
                u64t qb2 = *(const u64t*)(qp + 2);
                #pragma unroll
                for (int u = 0; u < 8; ++u) {
                    ffma2(acc2[i][u], qa, kva[u]);
                    ffma2(acc2[i][u], qb2, kvb[u]);
                }
            }
        }

        #pragma unroll
        for (int i = 0; i < 4; ++i) {
            int r = ty + 16*i;
            int qrow = qb*64 + r;
            float thr = vmin[r];
            #pragma unroll
            for (int u = 0; u < 8; ++u) {
                int g = kbase + tx + 16*u;
                float s = f2sum(acc2[i][u]);
                if ((g >> 4) == qrow) s = -1e9f;   // mask self (m == n)
                if (s > thr) {
                    topk_insert(sv, si, vmin, slock, r, s, g);
                    thr = vmin[r];
                }
            }
        }
        __syncthreads();
    }

    if (tid < 64) {
        int qrow = qb*64 + tid;
        #pragma unroll
        for (int e = 0; e < 10; ++e) {
            g_pv[qrow*80 + kb*10 + e] = sv[tid*10 + e];
            g_pi[qrow*80 + kb*10 + e] = si[tid*10 + e];
        }
    }
}

// ============================ K4: merge + softmax + gather + MLP ============================
__global__ void __launch_bounds__(256) final_kernel(
    const float* __restrict__ x,
    const float* __restrict__ W1, const float* __restrict__ b1,
    const float* __restrict__ W2, const float* __restrict__ b2,
    float* __restrict__ out)
{
    const int warp = threadIdx.x >> 5, lane = threadIdx.x & 31;
    const int n = blockIdx.x * 8 + warp;

    float cv[3]; int ci[3];
    #pragma unroll
    for (int s = 0; s < 3; ++s) {
        int c = lane + 32*s;
        if (c < 80) { cv[s] = g_pv[n*80 + c]; ci[s] = g_pi[n*80 + c]; }
        else        { cv[s] = -INFINITY;      ci[s] = -1000 - s; }
    }

    float topv[10]; int topi[10];
    #pragma unroll
    for (int it = 0; it < 10; ++it) {
        float bv = cv[0]; int bi = ci[0];
        if (cv[1] > bv || (cv[1] == bv && ci[1] < bi)) { bv = cv[1]; bi = ci[1]; }
        if (cv[2] > bv || (cv[2] == bv && ci[2] < bi)) { bv = cv[2]; bi = ci[2]; }
        #pragma unroll
        for (int off = 16; off; off >>= 1) {
            float ov = __shfl_xor_sync(0xffffffffu, bv, off);
            int   oi = __shfl_xor_sync(0xffffffffu, bi, off);
            if (ov > bv || (ov == bv && oi < bi)) { bv = ov; bi = oi; }
        }
        topv[it] = bv; topi[it] = bi;
        #pragma unroll
        for (int s = 0; s < 3; ++s)
            if (ci[s] == bi) { cv[s] = -INFINITY; ci[s] = -2000 - s; }
    }

    float w[10]; float sumw = 0.0f;
    #pragma unroll
    for (int e = 0; e < 10; ++e) { w[e] = __expf(topv[e] - topv[0]); sumw += w[e]; }
    float inv = 1.0f / sumw;

    if (lane < 16) {
        float wf = 0.0f;
        #pragma unroll
        for (int e = 0; e < 10; ++e) {
            int m  = topi[e] >> 4;
            int ti = 48 + (topi[e] & 15);
            wf = fmaf(w[e] * inv, x[(m*TT + ti)*FF + lane], wf);
        }
        float hid = b1[lane];
        #pragma unroll
        for (int f = 0; f < 16; ++f)
            hid = fmaf(W1[lane*16 + f], __shfl_sync(0xffffu, wf, f), hid);
        hid = hid > 0.0f ? hid : 0.01f * hid;
        float val = hid * W2[lane];
        #pragma unroll
        for (int off = 8; off; off >>= 1)
            val += __shfl_xor_sync(0xffffu, val, off);
        if (lane == 0) out[n] = val + b2[0];
    }
}

// ============================ launch ============================
extern "C" void kernel_launch(void* const* d_in, const int* in_sizes, int n_in,
                              void* d_out, int out_size)
{
    const float* x   = (const float*)d_in[0];
    const float* Wih = (const float*)d_in[1];
    const float* Whh = (const float*)d_in[2];
    const float* bih = (const float*)d_in[3];
    const float* bhh = (const float*)d_in[4];
    const float* Wq  = (const float*)d_in[5];
    const float* Wk  = (const float*)d_in[6];
    const float* W1  = (const float*)d_in[7];
    const float* b1  = (const float*)d_in[8];
    const float* W2  = (const float*)d_in[9];
    const float* b2  = (const float*)d_in[10];
    float* out = (float*)d_out;

    const int gru_smem = GRU_SMEM_FLOATS * 4;
    cudaFuncSetAttribute(gru_kernel, cudaFuncAttributeMaxDynamicSharedMemorySize, gru_smem);
    cudaFuncSetAttribute(scores_topk_kernel, cudaFuncAttributeMaxDynamicSharedMemorySize, K3_SMEM_BYTES);

    xp_kernel<<<NN*TT/32, 192>>>(x, Wih, bih);
    gru_kernel<<<NN/16, 256, gru_smem>>>(Whh, bhh);
    qk_kernel<<<NN, 256>>>(Wq, Wk);
    dim3 g3(NN/64, KBLOCKS);
    scores_topk_kernel<<<g3, 256, K3_SMEM_BYTES>>>();
    final_kernel<<<NN/8, 256>>>(x, W1, b1, W2, b2, out);
}